// round 12
// baseline (speedup 1.0000x reference)
#include <cuda_runtime.h>
#include <cstdint>
#include <climits>

constexpr int T = 512, B = 64, F = 32, K = 32;

#define FULL 0xffffffffu

__device__ int g_fw[B * 8];   // per-(batch,warp) feats watermark
__device__ int g_vw[B];       // per-batch viterbi watermark (maxs[<=vw] visible)

__device__ __forceinline__ float ex2f(float x) {
    float y; asm("ex2.approx.f32 %0, %1;" : "=f"(y) : "f"(x)); return y;
}
__device__ __forceinline__ float lg2f(float x) {
    float y; asm("lg2.approx.f32 %0, %1;" : "=f"(y) : "f"(x)); return y;
}
// acquire load WITH memory clobber: compiler may not hoist subsequent loads above it
__device__ __forceinline__ int ld_acq(const int* p) {
    int v; asm volatile("ld.acquire.gpu.global.s32 %0, [%1];" : "=r"(v) : "l"(p) : "memory");
    return v;
}
__device__ __forceinline__ void st_rel(int* p, int v) {
    asm volatile("st.release.gpu.global.s32 [%0], %1;" :: "l"(p), "r"(v) : "memory");
}
// plain coherent global load (NOT __ldg/nc — cross-SM produced data)
__device__ __forceinline__ float ld_f(const float* p) {
    float v; asm volatile("ld.global.f32 %0, [%1];" : "=f"(v) : "l"(p) : "memory");
    return v;
}

constexpr float L2E  = 1.4426950408889634f;
constexpr float LN2  = 0.6931471805599453f;
constexpr float LN32 = 3.4657359027997265f;

__global__ void reset_kernel() {
    int i = blockIdx.x * blockDim.x + threadIdx.x;
    if (i < B * 8) g_fw[i] = -1;
    if (i < B)     g_vw[i] = 0;      // maxs[0] provided by worker block itself
}

// grid = 128 blocks x 256 threads.
//   bid <  64 : chain block for batch b=bid.  Warp 6 = forward, warp 7 = viterbi,
//               warps 0-5 exit immediately -> only 2 live warps on this SM.
//   bid >= 64 : worker block for batch b=bid-64.  8 warps: feats column b
//               (striped t = w + 8i), then backpointers trailing g_vw.
__global__ void __launch_bounds__(256, 1)
crf_pipe(const int* __restrict__ words, const int* __restrict__ lens,
         const float* __restrict__ W, const float* __restrict__ trans,
         float* __restrict__ feats, float* __restrict__ maxs,
         float* __restrict__ idxo, float* __restrict__ score)
{
    int tid  = threadIdx.x;
    int wid  = tid >> 5;
    int lane = tid & 31;

    if (blockIdx.x >= 64) {
        // ========================= WORKER BLOCK =========================
        int b = blockIdx.x - 64;
        int L = __ldg(&lens[b]);
        int w = wid;

        // ---- phase A: feats rows t = w, w+8, ..., w+504 ----
        float w0v = __ldg(&W[0]) * 32.f;          // pad row value (idx -> 0)
        for (int i = 0; i < T / 8; i++) {
            int t = w + 8 * i;
            float s;
            if (t < L) {
                int gw = t * B + b;
                int wd = __ldg(&words[gw * F + lane]);
                float s0 = 0.f, s1 = 0.f, s2 = 0.f, s3 = 0.f;
#pragma unroll
                for (int f = 0; f < F; f += 4) {
                    int w0 = __shfl_sync(FULL, wd, f);
                    int w1 = __shfl_sync(FULL, wd, f + 1);
                    int w2 = __shfl_sync(FULL, wd, f + 2);
                    int w3 = __shfl_sync(FULL, wd, f + 3);
                    s0 += __ldg(&W[w0 + lane]); s1 += __ldg(&W[w1 + lane]);
                    s2 += __ldg(&W[w2 + lane]); s3 += __ldg(&W[w3 + lane]);
                }
                s = (s0 + s1) + (s2 + s3);
            } else {
                s = w0v;
            }
            feats[(t * B + b) * K + lane] = s;
            if (t == 0) {
                maxs[b * K + lane] = s;       // max_s[0] = feats[0]
                idxo[b * K + lane] = 0.f;     // max_s_idx[0] = 0
            }
            __threadfence();                  // order this lane's STGs (gpu scope)
            __syncwarp();
            if (lane == 0) st_rel(&g_fw[b * 8 + w], t);
        }
        // final release: unblock wait_fw(T-1)
        __syncwarp();
        if (lane == 0) st_rel(&g_fw[b * 8 + w], T);
        __syncthreads();                      // maxs[0]/idxo[0] visible to bp warps

        // ---- phase B: backpointers, stripe t = 1+w, 9+w, ... ----
        float tc[K];
#pragma unroll
        for (int j = 0; j < K; j++) tc[j] = __ldg(&trans[j * K + lane]);

        int Lc = (L < T) ? L : T;
        for (int t = 1 + w; t < Lc; t += 8) {
            while (ld_acq(&g_vw[b]) < t - 1) __nanosleep(64);
            float dp = ld_f(&maxs[((t - 1) * B + b) * K + lane]);   // coherent
            float best = __shfl_sync(FULL, dp, 0) + tc[0];
            int   bi   = 0;
#pragma unroll
            for (int j = 1; j < K; j++) {
                float sc = __shfl_sync(FULL, dp, j) + tc[j];
                if (sc > best) { best = sc; bi = j; }   // strict > : first index
            }
            idxo[(t * B + b) * K + lane] = (float)bi;
        }
        if (L < T) {
            while (ld_acq(&g_vw[b]) < L - 1) __nanosleep(64);
            float dp = ld_f(&maxs[((L - 1) * B + b) * K + lane]);   // coherent
            float best = __shfl_sync(FULL, dp, 0) + tc[0];
            int   bi   = 0;
#pragma unroll
            for (int j = 1; j < K; j++) {
                float sc = __shfl_sync(FULL, dp, j) + tc[j];
                if (sc > best) { best = sc; bi = j; }
            }
            float v = (float)bi;
            int s0i = 1 + w;
            int t0  = (L > s0i) ? s0i + ((L - s0i + 7) / 8) * 8 : s0i;
#pragma unroll 4
            for (int t = t0; t < T; t += 8)
                idxo[(t * B + b) * K + lane] = v;
        }
        return;
    }

    // ========================= CHAIN BLOCK =========================
    int b = blockIdx.x;
    if (wid < 6) return;                      // only warps 6,7 stay alive
    int L = __ldg(&lens[b]);

    auto wait_fw = [&](int need) {
        for (;;) {
            int m = INT_MAX;
#pragma unroll
            for (int u = 0; u < 8; u++) m = min(m, ld_acq(&g_fw[b * 8 + u]));
            if (m >= need) break;
        }
    };

    if (wid == 6) {
        // ---------------- forward chain (linear domain) ----------------
        float et[K];
#pragma unroll
        for (int j = 0; j < K; j++) et[j] = ex2f(__ldg(&trans[j * K + lane]) * L2E);

        wait_fw(min(34, T - 1));
        float f0 = ld_f(&feats[b * K + lane]);
        float C0 = __shfl_sync(FULL, f0, 0);
        float E    = ex2f((f0 - C0) * L2E);
        float Ctot = C0;

        float fA = ld_f(&feats[(1 * B + b) * K + lane]);
        float fB = ld_f(&feats[(2 * B + b) * K + lane]);

        for (int base = 1; base < L; base += 32) {
            wait_fw(min(base + 34, T - 1));
            int end = min(base + 32, L);
            for (int t = base; t < end; t++) {
                float f = fA;
                fA = fB;
                int tp = min(t + 2, T - 1);
                fB = ld_f(&feats[(tp * B + b) * K + lane]);
                float xf = ex2f(fmaf(f, L2E, -5.f));      // exp(f)/32, off-path

                float s0 = 0.f, s1 = 0.f, s2 = 0.f, s3 = 0.f;
#pragma unroll
                for (int j = 0; j < K; j += 4) {
                    s0 = fmaf(__shfl_sync(FULL, E, j),     et[j],     s0);
                    s1 = fmaf(__shfl_sync(FULL, E, j + 1), et[j + 1], s1);
                    s2 = fmaf(__shfl_sync(FULL, E, j + 2), et[j + 2], s2);
                    s3 = fmaf(__shfl_sync(FULL, E, j + 3), et[j + 3], s3);
                }
                E = ((s0 + s1) + (s2 + s3)) * xf;
                Ctot += LN32;
                if ((t & 127) == 0) {                     // renorm (alpha-preserving)
                    float rr = __shfl_sync(FULL, E, 0);
                    float cc = lg2f(rr);
                    E *= ex2f(-cc);
                    Ctot += cc * LN2;
                }
            }
        }
        float e = E;
#pragma unroll
        for (int o = 16; o; o >>= 1) e += __shfl_xor_sync(FULL, e, o);
        if (lane == 0) score[b] = Ctot + lg2f(e) * LN2;

    } else {
        // ---------------- Viterbi chain ----------------
        float tc[K];
#pragma unroll
        for (int j = 0; j < K; j++) tc[j] = __ldg(&trans[j * K + lane]);

        wait_fw(min(34, T - 1));
        float delta = ld_f(&feats[b * K + lane]);

        float fA = ld_f(&feats[(1 * B + b) * K + lane]);
        float fB = ld_f(&feats[(2 * B + b) * K + lane]);

        for (int base = 1; base < L; base += 32) {
            wait_fw(min(base + 34, T - 1));
            int end = min(base + 32, L);
            for (int t = base; t < end; t++) {
                float f = fA;
                fA = fB;
                int tp = min(t + 2, T - 1);
                fB = ld_f(&feats[(tp * B + b) * K + lane]);

                const float NEG_INF = __int_as_float(0xff800000);
                float m0 = NEG_INF, m1 = NEG_INF, m2 = NEG_INF, m3 = NEG_INF;
#pragma unroll
                for (int j = 0; j < K; j += 4) {
                    m0 = fmaxf(m0, __shfl_sync(FULL, delta, j)     + tc[j]);
                    m1 = fmaxf(m1, __shfl_sync(FULL, delta, j + 1) + tc[j + 1]);
                    m2 = fmaxf(m2, __shfl_sync(FULL, delta, j + 2) + tc[j + 2]);
                    m3 = fmaxf(m3, __shfl_sync(FULL, delta, j + 3) + tc[j + 3]);
                }
                delta = fmaxf(fmaxf(m0, m1), fmaxf(m2, m3)) + f;
                maxs[(t * B + b) * K + lane] = delta;

                if ((t & 15) == 0) {                      // publish watermark
                    __threadfence();
                    __syncwarp();
                    if (lane == 0) st_rel(&g_vw[b], t - 1);
                }
            }
        }
        // release everything computed so far (unblocks bp up to L-1)
        __threadfence();
        __syncwarp();
        if (lane == 0) st_rel(&g_vw[b], L - 1);

        // frozen tail: max_s[t] = delta for t in [L, T)
#pragma unroll 4
        for (int t = L; t < T; t++)
            maxs[(t * B + b) * K + lane] = delta;
        __threadfence();
        __syncwarp();
        if (lane == 0) st_rel(&g_vw[b], T);
    }
}

// ---------------------------------------------------------------------------
extern "C" void kernel_launch(void* const* d_in, const int* in_sizes, int n_in,
                              void* d_out, int out_size) {
    const int*   words = (const int*)d_in[0];     // [T,B,F] int32
    const int*   lens  = (const int*)d_in[1];     // [B] int32
    const float* W     = (const float*)d_in[2];   // [1e6] f32
    const float* trans = (const float*)d_in[3];   // [K,K] f32
    float* out   = (float*)d_out;
    float* score = out;
    float* maxs  = out + 64;
    float* idxo  = out + 64 + T * B * K;
    float* feats = out + 64 + 2 * T * B * K;

    reset_kernel<<<2, 256>>>();
    crf_pipe<<<128, 256>>>(words, lens, W, trans, feats, maxs, idxo, score);
}

// round 13
// speedup vs baseline: 1.4690x; 1.4690x over previous
#include <cuda_runtime.h>
#include <cstdint>

constexpr int T = 512, B = 64, F = 32, K = 32;

#define FULL 0xffffffffu
#define VOLI(x) (*(volatile int*)&(x))

__device__ __forceinline__ float ex2f(float x) {
    float y; asm("ex2.approx.f32 %0, %1;" : "=f"(y) : "f"(x)); return y;
}
__device__ __forceinline__ float lg2f(float x) {
    float y; asm("lg2.approx.f32 %0, %1;" : "=f"(y) : "f"(x)); return y;
}
__device__ __forceinline__ uint32_t s2u(const void* p) {
    uint32_t a;
    asm("{ .reg .u64 t; cvta.to.shared.u64 t, %1; cvt.u32.u64 %0, t; }"
        : "=r"(a) : "l"(p));
    return a;
}

constexpr float L2E  = 1.4426950408889634f;
constexpr float LN2  = 0.6931471805599453f;
constexpr float LN32 = 3.4657359027997265f;

// ---------------------------------------------------------------------------
// Kernel 1: emission feats.  One warp per (t,b); lane = tag k.  (R7 verbatim)
// ---------------------------------------------------------------------------
__global__ void feats_kernel(const int* __restrict__ words,
                             const int* __restrict__ lens,
                             const float* __restrict__ W,
                             float* __restrict__ feats,
                             float* __restrict__ maxs,
                             float* __restrict__ idxo) {
    int gw   = (blockIdx.x * blockDim.x + threadIdx.x) >> 5;   // t*B + b
    int lane = threadIdx.x & 31;
    if (gw >= T * B) return;
    int t = gw >> 6;
    int b = gw & 63;

    int L = __ldg(&lens[b]);
    bool valid = (t < L);

    int w = valid ? __ldg(&words[gw * F + lane]) : 0;

    float s0 = 0.f, s1 = 0.f, s2 = 0.f, s3 = 0.f;
#pragma unroll
    for (int f = 0; f < F; f += 4) {
        int w0 = __shfl_sync(FULL, w, f);
        int w1 = __shfl_sync(FULL, w, f + 1);
        int w2 = __shfl_sync(FULL, w, f + 2);
        int w3 = __shfl_sync(FULL, w, f + 3);
        int i0 = valid ? (w0 + lane) : 0;   // mask AFTER tag shift (ref semantics)
        int i1 = valid ? (w1 + lane) : 0;
        int i2 = valid ? (w2 + lane) : 0;
        int i3 = valid ? (w3 + lane) : 0;
        s0 += __ldg(&W[i0]); s1 += __ldg(&W[i1]);
        s2 += __ldg(&W[i2]); s3 += __ldg(&W[i3]);
    }
    float s = (s0 + s1) + (s2 + s3);

    feats[gw * K + lane] = s;
    if (t == 0) {
        maxs[b * K + lane] = s;     // max_s[0] = feats[0]
        idxo[b * K + lane] = 0.f;   // max_s_idx[0] = 0
    }
}

// ---------------------------------------------------------------------------
// Kernel 2: recurrence + backpointers.  One block per batch, 4 warps:
//   wid 3  : MERGED chain warp — forward (linear domain) AND Viterbi
//            interleaved over the same t: vit's instructions fill fwd's
//            stall cycles (R7 profile: each chain warp only issued 30%).
//   wid 2  : exits immediately.
//   wid 0,1: backpointer consumers trailing the chain via s_vw watermark.
// feats streamed into smem in 128-step chunks via cp.async (double buffer).
// ---------------------------------------------------------------------------
__global__ void __launch_bounds__(128, 1)
rec_kernel(const float* __restrict__ trans,
           const int* __restrict__ lens,
           const float* __restrict__ feats,
           float* __restrict__ maxs,
           float* __restrict__ idxo,
           float* __restrict__ score) {
    __shared__ __align__(16) float sf[2][128][K];   // 32 KB feats double buffer
    __shared__ int s_vw;                             // maxs[<=s_vw] visible

    int tid  = threadIdx.x;
    int wid  = tid >> 5;
    int lane = tid & 31;
    int b    = blockIdx.x;

    if (tid == 0) s_vw = 0;           // maxs[0] written by feats_kernel
    __syncthreads();

    int L = __ldg(&lens[b]);          // uniform within block

    float tc[K];                      // trans[j][lane]
#pragma unroll
    for (int j = 0; j < K; j++) tc[j] = __ldg(&trans[j * K + lane]);

    if (wid == 2) return;

    if (wid == 3) {
        // ================= merged chain warp =================
        auto issue_chunk = [&](int c) {
            const float* base = feats + (c * 128) * (B * K) + b * K;
#pragma unroll
            for (int i = 0; i < 32; i++) {
                int op  = lane + 32 * i;        // 0..1023 16B ops
                int row = op >> 3, seg = op & 7;
                const float* src = base + row * (B * K) + seg * 4;
                uint32_t dst = s2u(&sf[c & 1][row][seg * 4]);
                asm volatile("cp.async.ca.shared.global [%0], [%1], 16;"
                             :: "r"(dst), "l"(src));
            }
            asm volatile("cp.async.commit_group;");
        };

        issue_chunk(0);
        issue_chunk(1);
        asm volatile("cp.async.wait_group 1;");     // chunk 0 ready (same warp)

        float f0 = sf[0][0][lane];

        // forward state (linear domain)
        float et[K];
#pragma unroll
        for (int j = 0; j < K; j++) et[j] = ex2f(tc[j] * L2E);
        float C0   = __shfl_sync(FULL, f0, 0);
        float E    = ex2f((f0 - C0) * L2E);
        float Ctot = C0;
        // viterbi state
        float delta = f0;

        const float NEG_INF = __int_as_float(0xff800000);
        bool done = false;
        for (int c = 0; c < 4 && !done; c++) {
            const float (*fb)[K] = sf[c & 1];
            int r0 = (c == 0) ? 1 : 0;
            for (int r = r0; r < 128; r++) {
                int t = c * 128 + r;
                if (t >= L) { done = true; break; }
                float f  = fb[r][lane];
                float xf = ex2f(fmaf(f, L2E, -5.f));     // exp(f)/32

                // interleaved fwd matvec + vit max — independent dep chains
                float s0 = 0.f, s1 = 0.f, s2 = 0.f, s3 = 0.f;
                float m0 = NEG_INF, m1 = NEG_INF, m2 = NEG_INF, m3 = NEG_INF;
#pragma unroll
                for (int j = 0; j < K; j += 4) {
                    float e0 = __shfl_sync(FULL, E, j);
                    float d0 = __shfl_sync(FULL, delta, j);
                    float e1 = __shfl_sync(FULL, E, j + 1);
                    float d1 = __shfl_sync(FULL, delta, j + 1);
                    float e2 = __shfl_sync(FULL, E, j + 2);
                    float d2 = __shfl_sync(FULL, delta, j + 2);
                    float e3 = __shfl_sync(FULL, E, j + 3);
                    float d3 = __shfl_sync(FULL, delta, j + 3);
                    s0 = fmaf(e0, et[j],     s0);  m0 = fmaxf(m0, d0 + tc[j]);
                    s1 = fmaf(e1, et[j + 1], s1);  m1 = fmaxf(m1, d1 + tc[j + 1]);
                    s2 = fmaf(e2, et[j + 2], s2);  m2 = fmaxf(m2, d2 + tc[j + 2]);
                    s3 = fmaf(e3, et[j + 3], s3);  m3 = fmaxf(m3, d3 + tc[j + 3]);
                }
                E = (((s0 + s1) + (s2 + s3))) * xf;
                Ctot += LN32;
                delta = fmaxf(fmaxf(m0, m1), fmaxf(m2, m3)) + f;
                maxs[(t * B + b) * K + lane] = delta;

                if ((t & 127) == 0) {                    // fwd renorm
                    float rr = __shfl_sync(FULL, E, 0);
                    float cc = lg2f(rr);
                    E *= ex2f(-cc);
                    Ctot += cc * LN2;
                }
                if ((t & 15) == 0) {                     // publish to bp warps
                    __syncwarp();
                    __threadfence_block();
                    if (lane == 0) VOLI(s_vw) = t;
                    __syncwarp();
                }
            }
            if (!done && c < 3) {
                asm volatile("cp.async.wait_group 0;");  // next chunk ready
                if (c < 2) issue_chunk(c + 2);
            }
        }
        asm volatile("cp.async.wait_group 0;");          // drain

        // forward score
        float e = E;
#pragma unroll
        for (int o = 16; o; o >>= 1) e += __shfl_xor_sync(FULL, e, o);
        if (lane == 0) score[b] = Ctot + lg2f(e) * LN2;

        // unblock bp up to L-1, then frozen tail
        __syncwarp();
        __threadfence_block();
        if (lane == 0) VOLI(s_vw) = L - 1;
        __syncwarp();
#pragma unroll 4
        for (int t = L; t < T; t++)
            maxs[(t * B + b) * K + lane] = delta;
        __syncwarp();
        __threadfence_block();
        if (lane == 0) VOLI(s_vw) = T;                   // final release

    } else {
        // ================= backpointer warps (wid 0,1) =================
        int q = wid;                                  // t parity (1+q) mod 2
        int Lc = (L < T) ? L : T;

        for (int t = 1 + q; t < Lc; t += 2) {
            while (VOLI(s_vw) < t - 1) __nanosleep(32);
            __threadfence_block();
            float dp = maxs[((t - 1) * B + b) * K + lane];

            float best = __shfl_sync(FULL, dp, 0) + tc[0];
            int   bi   = 0;
#pragma unroll
            for (int j = 1; j < K; j++) {
                float sc = __shfl_sync(FULL, dp, j) + tc[j];
                if (sc > best) { best = sc; bi = j; }  // strict > keeps first index
            }
            idxo[(t * B + b) * K + lane] = (float)bi;
        }

        if (L < T) {
            // frozen region: bp constant, computed once from maxs[L-1]
            while (VOLI(s_vw) < L - 1) __nanosleep(32);
            __threadfence_block();
            float dp = maxs[((L - 1) * B + b) * K + lane];

            float best = __shfl_sync(FULL, dp, 0) + tc[0];
            int   bi   = 0;
#pragma unroll
            for (int j = 1; j < K; j++) {
                float sc = __shfl_sync(FULL, dp, j) + tc[j];
                if (sc > best) { best = sc; bi = j; }
            }
            float v = (float)bi;
            int t0 = L + (((1 + q) - L) & 1);          // first t>=L, right parity
            if (t0 < 1 + q) t0 = 1 + q;
#pragma unroll 4
            for (int t = t0; t < T; t += 2)
                idxo[(t * B + b) * K + lane] = v;
        }
    }
}

// ---------------------------------------------------------------------------
extern "C" void kernel_launch(void* const* d_in, const int* in_sizes, int n_in,
                              void* d_out, int out_size) {
    const int*   words = (const int*)d_in[0];     // [T,B,F] int32
    const int*   lens  = (const int*)d_in[1];     // [B] int32
    const float* W     = (const float*)d_in[2];   // [1e6] f32
    const float* trans = (const float*)d_in[3];   // [K,K] f32
    float* out   = (float*)d_out;
    float* score = out;
    float* maxs  = out + 64;
    float* idxo  = out + 64 + T * B * K;
    float* feats = out + 64 + 2 * T * B * K;

    feats_kernel<<<(T * B) / 8, 256>>>(words, lens, W, feats, maxs, idxo);
    rec_kernel<<<B, 128>>>(trans, lens, feats, maxs, idxo, score);
}